// round 2
// baseline (speedup 1.0000x reference)
#include <cuda_runtime.h>
#include <math.h>
#include <stdint.h>

#define HW      56
#define NPIX    3136          // 56*56
#define CDIM    256
#define HEADS   8
#define HD      32
#define NPAIR   16            // HD/2
#define BATCH   2
#define MROWS   (BATCH*NPIX)  // 6272
#define WIN     7
#define RAD     3

// -------- scratch (static device allocations; no cudaMalloc anywhere) --------
__device__ float g_q[BATCH*HEADS*NPIX*HD];
__device__ float g_k[BATCH*HEADS*NPIX*HD];
__device__ float g_v[BATCH*HEADS*NPIX*HD];
__device__ float g_attn[BATCH*NPIX*CDIM];
__device__ float g_cos[NPIX*NPAIR];
__device__ float g_sin[NPIX*NPAIR];

// ---------------- RoPE tables (double precision, matches numpy) ----------------
__global__ void rope_table_kernel() {
    int idx = blockIdx.x * blockDim.x + threadIdx.x;
    if (idx >= NPIX * NPAIR) return;
    int p = idx & (NPAIR - 1);
    int n = idx >> 4;
    double inv = pow(10000.0, -(double)p / 16.0);
    double ang = (double)n * inv;
    double s, c;
    sincos(ang, &s, &c);
    g_cos[idx] = (float)c;
    g_sin[idx] = (float)s;
}

// ---------------- QKV GEMM (M=6272, N=768, K=256) fused with RoPE ----------------
// BM=128, BN=64, BK=16, 256 threads, 8x4 acc per thread.
__global__ void __launch_bounds__(256) qkv_rope_gemm(
    const float* __restrict__ X, const float* __restrict__ W)
{
    __shared__ float As[16][132];   // [k][m], padded
    __shared__ float Bs[16][68];    // [k][n], padded

    const int tid = threadIdx.x;
    const int mBase = blockIdx.y * 128;
    const int nBase = blockIdx.x * 64;

    const int arow = tid >> 2;            // 0..63
    const int ak4  = (tid & 3) * 4;
    const int brow = tid >> 4;            // 0..15
    const int bcol4 = (tid & 15) * 4;
    const int ty = tid >> 4;              // 0..15
    const int tx = tid & 15;              // 0..15

    float acc[8][4];
#pragma unroll
    for (int i = 0; i < 8; i++)
#pragma unroll
        for (int j = 0; j < 4; j++) acc[i][j] = 0.f;

    for (int kt = 0; kt < 256; kt += 16) {
        __syncthreads();
        float4 av0 = *(const float4*)(X + (size_t)(mBase + arow)      * 256 + kt + ak4);
        float4 av1 = *(const float4*)(X + (size_t)(mBase + arow + 64) * 256 + kt + ak4);
        As[ak4 + 0][arow] = av0.x; As[ak4 + 1][arow] = av0.y;
        As[ak4 + 2][arow] = av0.z; As[ak4 + 3][arow] = av0.w;
        As[ak4 + 0][arow + 64] = av1.x; As[ak4 + 1][arow + 64] = av1.y;
        As[ak4 + 2][arow + 64] = av1.z; As[ak4 + 3][arow + 64] = av1.w;
        float4 bv = *(const float4*)(W + (size_t)(kt + brow) * 768 + nBase + bcol4);
        *(float4*)&Bs[brow][bcol4] = bv;
        __syncthreads();

#pragma unroll
        for (int kk = 0; kk < 16; kk++) {
            float4 a0 = *(const float4*)&As[kk][ty * 8];
            float4 a1 = *(const float4*)&As[kk][ty * 8 + 4];
            float4 b  = *(const float4*)&Bs[kk][tx * 4];
            float ar[8] = {a0.x, a0.y, a0.z, a0.w, a1.x, a1.y, a1.z, a1.w};
            float br[4] = {b.x, b.y, b.z, b.w};
#pragma unroll
            for (int i = 0; i < 8; i++)
#pragma unroll
                for (int j = 0; j < 4; j++)
                    acc[i][j] = fmaf(ar[i], br[j], acc[i][j]);
        }
    }

    // epilogue: RoPE + scatter to g_q/g_k/g_v [b, head, n, d]
    const int col0 = nBase + tx * 4;         // multiple of 4; 4-col group within one head
    const int which = col0 >> 8;             // 0=q, 1=k, 2=v
    const int rem  = col0 & 255;
    const int head = rem >> 5;
    const int d0   = rem & 31;
    float* dst = (which == 0) ? g_q : (which == 1) ? g_k : g_v;

#pragma unroll
    for (int ii = 0; ii < 8; ii++) {
        int grow = mBase + ty * 8 + ii;
        int b = grow / NPIX;
        int n = grow - b * NPIX;
        size_t base = ((size_t)(b * HEADS + head) * NPIX + n) * HD + d0;
        float x0 = acc[ii][0], x1 = acc[ii][1], x2 = acc[ii][2], x3 = acc[ii][3];
        if (which < 2) {
            int p0 = d0 >> 1;
            float c0 = g_cos[n * NPAIR + p0],     s0 = g_sin[n * NPAIR + p0];
            float c1 = g_cos[n * NPAIR + p0 + 1], s1 = g_sin[n * NPAIR + p0 + 1];
            dst[base + 0] = x0 * c0 - x1 * s0;
            dst[base + 1] = x1 * c0 + x0 * s0;
            dst[base + 2] = x2 * c1 - x3 * s1;
            dst[base + 3] = x3 * c1 + x2 * s1;
        } else {
            dst[base + 0] = x0; dst[base + 1] = x1;
            dst[base + 2] = x2; dst[base + 3] = x3;
        }
    }
}

// ---------------- Neighborhood attention ----------------
// grid = (H, B*heads). Block = 256 threads (8 warps), warp per query (7 queries/warp).
// smem stages the 7x56 key/value band (fp32): 2 * 12544 floats = 100352 B.
__global__ void __launch_bounds__(256) attn_kernel() {
    extern __shared__ float sm[];
    float* ks = sm;
    float* vs = sm + WIN * HW * HD;   // 12544

    const int i  = blockIdx.x;        // query row
    const int bh = blockIdx.y;        // b*8 + h
    const int tid = threadIdx.x;
    const int w = tid >> 5;
    const int lane = tid & 31;

    const int r0 = min(max(i - RAD, 0), HW - WIN);

    const float4* k4 = (const float4*)(g_k + ((size_t)bh * NPIX + r0 * HW) * HD);
    const float4* v4 = (const float4*)(g_v + ((size_t)bh * NPIX + r0 * HW) * HD);
    float4* ks4 = (float4*)ks;
    float4* vs4 = (float4*)vs;
    for (int idx = tid; idx < WIN * HW * HD / 4; idx += 256) {
        ks4[idx] = k4[idx];
        vs4[idx] = v4[idx];
    }
    __syncthreads();

    const float scale = 0.17677669529663688f;  // 32^-0.5
    const int b = bh >> 3;
    const int h = bh & 7;

    for (int t = 0; t < WIN; t++) {
        int jq = w * WIN + t;                  // 8 warps * 7 = 56 queries
        float qv = g_q[((size_t)bh * NPIX + i * HW + jq) * HD + lane];
        int c0 = min(max(jq - RAD, 0), HW - WIN);

        float m = -1e30f, l = 0.f, o = 0.f;
        for (int rr = 0; rr < WIN; rr++) {
            int rowoff = rr * HW + c0;
#pragma unroll
            for (int cc = 0; cc < WIN; cc++) {
                int off = (rowoff + cc) * HD;
                float s = qv * ks[off + lane];
                s += __shfl_xor_sync(0xffffffffu, s, 16);
                s += __shfl_xor_sync(0xffffffffu, s, 8);
                s += __shfl_xor_sync(0xffffffffu, s, 4);
                s += __shfl_xor_sync(0xffffffffu, s, 2);
                s += __shfl_xor_sync(0xffffffffu, s, 1);
                s *= scale;
                float mn = fmaxf(m, s);
                float corr = __expf(m - mn);
                float p = __expf(s - mn);
                l = l * corr + p;
                o = o * corr + p * vs[off + lane];
                m = mn;
            }
        }
        // write [B, N, C] layout for the projection GEMM
        g_attn[((size_t)b * NPIX + i * HW + jq) * CDIM + h * HD + lane] = o / l;
    }
}

// ---------------- Projection GEMM (M=6272, N=256, K=256) + bias ----------------
__global__ void __launch_bounds__(256) proj_gemm(
    const float* __restrict__ W, const float* __restrict__ bias, float* __restrict__ out)
{
    __shared__ float As[16][132];
    __shared__ float Bs[16][68];

    const int tid = threadIdx.x;
    const int mBase = blockIdx.y * 128;
    const int nBase = blockIdx.x * 64;

    const int arow = tid >> 2;
    const int ak4  = (tid & 3) * 4;
    const int brow = tid >> 4;
    const int bcol4 = (tid & 15) * 4;
    const int ty = tid >> 4;
    const int tx = tid & 15;

    float acc[8][4];
#pragma unroll
    for (int i = 0; i < 8; i++)
#pragma unroll
        for (int j = 0; j < 4; j++) acc[i][j] = 0.f;

    for (int kt = 0; kt < 256; kt += 16) {
        __syncthreads();
        float4 av0 = *(const float4*)(g_attn + (size_t)(mBase + arow)      * 256 + kt + ak4);
        float4 av1 = *(const float4*)(g_attn + (size_t)(mBase + arow + 64) * 256 + kt + ak4);
        As[ak4 + 0][arow] = av0.x; As[ak4 + 1][arow] = av0.y;
        As[ak4 + 2][arow] = av0.z; As[ak4 + 3][arow] = av0.w;
        As[ak4 + 0][arow + 64] = av1.x; As[ak4 + 1][arow + 64] = av1.y;
        As[ak4 + 2][arow + 64] = av1.z; As[ak4 + 3][arow + 64] = av1.w;
        float4 bv = *(const float4*)(W + (size_t)(kt + brow) * 256 + nBase + bcol4);
        *(float4*)&Bs[brow][bcol4] = bv;
        __syncthreads();

#pragma unroll
        for (int kk = 0; kk < 16; kk++) {
            float4 a0 = *(const float4*)&As[kk][ty * 8];
            float4 a1 = *(const float4*)&As[kk][ty * 8 + 4];
            float4 b  = *(const float4*)&Bs[kk][tx * 4];
            float ar[8] = {a0.x, a0.y, a0.z, a0.w, a1.x, a1.y, a1.z, a1.w};
            float br[4] = {b.x, b.y, b.z, b.w};
#pragma unroll
            for (int i = 0; i < 8; i++)
#pragma unroll
                for (int j = 0; j < 4; j++)
                    acc[i][j] = fmaf(ar[i], br[j], acc[i][j]);
        }
    }

    const int col0 = nBase + tx * 4;
    float4 bv = *(const float4*)(bias + col0);
#pragma unroll
    for (int ii = 0; ii < 8; ii++) {
        int grow = mBase + ty * 8 + ii;
        float4 r;
        r.x = acc[ii][0] + bv.x;
        r.y = acc[ii][1] + bv.y;
        r.z = acc[ii][2] + bv.z;
        r.w = acc[ii][3] + bv.w;
        *(float4*)(out + (size_t)grow * 256 + col0) = r;
    }
}

// ---------------- launch ----------------
extern "C" void kernel_launch(void* const* d_in, const int* in_sizes, int n_in,
                              void* d_out, int out_size)
{
    const float* x     = (const float*)d_in[0];
    const float* Wqkv  = (const float*)d_in[1];
    const float* Wproj = (const float*)d_in[2];
    const float* bproj = (const float*)d_in[3];
    float* out = (float*)d_out;

    static bool attr_set = false;
    if (!attr_set) {
        cudaFuncSetAttribute(attn_kernel, cudaFuncAttributeMaxDynamicSharedMemorySize,
                             2 * WIN * HW * HD * (int)sizeof(float));
        attr_set = true;
    }

    rope_table_kernel<<<(NPIX * NPAIR + 255) / 256, 256>>>();
    qkv_rope_gemm<<<dim3(768 / 64, MROWS / 128), 256>>>(x, Wqkv);
    attn_kernel<<<dim3(HW, BATCH * HEADS), 256, 2 * WIN * HW * HD * (int)sizeof(float)>>>();
    proj_gemm<<<dim3(256 / 64, MROWS / 128), 256>>>(Wproj, bproj, out);
}

// round 4
// speedup vs baseline: 1.7307x; 1.7307x over previous
#include <cuda_runtime.h>
#include <cuda_bf16.h>
#include <math.h>
#include <stdint.h>

#define HW    56
#define NPIX  3136
#define CDIM  256
#define HEADS 8
#define HD    32
#define NPAIR 16
#define BATCH 2
#define MROWS (BATCH*NPIX)
#define WIN   7
#define RAD   3

__device__ float g_q[BATCH*HEADS*NPIX*HD];
__device__ float g_k[BATCH*HEADS*NPIX*HD];
__device__ float g_v[BATCH*HEADS*NPIX*HD];
__device__ float g_cos[NPIX*NPAIR];
__device__ float g_sin[NPIX*NPAIR];
__device__ __nv_bfloat16 g_Xhi[MROWS*CDIM];
__device__ __nv_bfloat16 g_Xlo[MROWS*CDIM];
__device__ __nv_bfloat16 g_Wqt_hi[768*CDIM];
__device__ __nv_bfloat16 g_Wqt_lo[768*CDIM];
__device__ __nv_bfloat16 g_Wpt_hi[CDIM*CDIM];
__device__ __nv_bfloat16 g_Wpt_lo[CDIM*CDIM];
__device__ __nv_bfloat16 g_attnhi[MROWS*CDIM];
__device__ __nv_bfloat16 g_attnlo[MROWS*CDIM];

// ---------- prep: rope tables + bf16 hi/lo splits + W transposes ----------
#define SEG0 (NPIX*NPAIR)
#define SEG1 (SEG0 + MROWS*CDIM)
#define SEG2 (SEG1 + 768*CDIM)
#define SEG3 (SEG2 + CDIM*CDIM)

__global__ void prep_kernel(const float* __restrict__ X, const float* __restrict__ Wq,
                            const float* __restrict__ Wp) {
    int idx = blockIdx.x * 256 + threadIdx.x;
    if (idx < SEG0) {
        int p = idx & 15, n = idx >> 4;
        double inv = pow(10000.0, -(double)p / 16.0);
        double s, c;
        sincos((double)n * inv, &s, &c);
        g_cos[idx] = (float)c; g_sin[idx] = (float)s;
    } else if (idx < SEG1) {
        int j = idx - SEG0;
        float x = X[j];
        __nv_bfloat16 hi = __float2bfloat16(x);
        g_Xhi[j] = hi; g_Xlo[j] = __float2bfloat16(x - __bfloat162float(hi));
    } else if (idx < SEG2) {
        int j = idx - SEG1;
        int n = j >> 8, k = j & 255;
        float x = Wq[k * 768 + n];
        __nv_bfloat16 hi = __float2bfloat16(x);
        g_Wqt_hi[j] = hi; g_Wqt_lo[j] = __float2bfloat16(x - __bfloat162float(hi));
    } else if (idx < SEG3) {
        int j = idx - SEG2;
        int n = j >> 8, k = j & 255;
        float x = Wp[k * 256 + n];
        __nv_bfloat16 hi = __float2bfloat16(x);
        g_Wpt_hi[j] = hi; g_Wpt_lo[j] = __float2bfloat16(x - __bfloat162float(hi));
    }
}

// ---------- mma.sync helpers ----------
__device__ __forceinline__ uint32_t lds_u32(const void* p) {
    return (uint32_t)__cvta_generic_to_shared(p);
}
__device__ __forceinline__ void ldmatrix_x4(uint32_t* r, uint32_t addr) {
    asm volatile("ldmatrix.sync.aligned.m8n8.x4.shared.b16 {%0,%1,%2,%3}, [%4];"
                 : "=r"(r[0]), "=r"(r[1]), "=r"(r[2]), "=r"(r[3]) : "r"(addr));
}
__device__ __forceinline__ void mma16816(float* c, const uint32_t* a, uint32_t b0, uint32_t b1) {
    asm volatile("mma.sync.aligned.m16n8k16.row.col.f32.bf16.bf16.f32 "
                 "{%0,%1,%2,%3}, {%4,%5,%6,%7}, {%8,%9}, {%0,%1,%2,%3};"
                 : "+f"(c[0]), "+f"(c[1]), "+f"(c[2]), "+f"(c[3])
                 : "r"(a[0]), "r"(a[1]), "r"(a[2]), "r"(a[3]), "r"(b0), "r"(b1));
}

// ---------- GEMM: D[128x128] = A[128x256] @ B[128x256]^T via bf16 split ----------
// mode 0: A=X split, B=Wqkv^T split, epilogue RoPE + scatter to g_q/g_k/g_v
// mode 1: A=attn split, B=Wproj^T split, epilogue bias -> out
__global__ void __launch_bounds__(256) gemm_mma(int mode, const float* __restrict__ bias,
                                                float* __restrict__ out) {
    __shared__ __nv_bfloat16 As[128][72];
    __shared__ __nv_bfloat16 Bs[128][72];

    const int tid = threadIdx.x, wid = tid >> 5, lane = tid & 31;
    const int warp_m = wid & 3, warp_n = wid >> 2;
    const int mBase = blockIdx.y * 128, nBase = blockIdx.x * 128;

    const __nv_bfloat16 *Ah, *Al, *Bh, *Bl;
    if (mode) { Ah = g_attnhi; Al = g_attnlo; Bh = g_Wpt_hi; Bl = g_Wpt_lo; }
    else      { Ah = g_Xhi;    Al = g_Xlo;    Bh = g_Wqt_hi; Bl = g_Wqt_lo; }

    float acc[2][8][4];
#pragma unroll
    for (int i = 0; i < 2; i++)
#pragma unroll
        for (int j = 0; j < 8; j++)
#pragma unroll
            for (int k = 0; k < 4; k++) acc[i][j][k] = 0.f;

    // ldmatrix source addresses (fixed per thread)
    uint32_t a_addr[2], b_addr[4];
#pragma unroll
    for (int mi = 0; mi < 2; mi++)
        a_addr[mi] = lds_u32(&As[warp_m * 32 + mi * 16 + (lane & 15)][(lane >> 4) << 3]);
#pragma unroll
    for (int np = 0; np < 4; np++)
        b_addr[np] = lds_u32(&Bs[warp_n * 64 + np * 16 + ((lane >> 4) << 3) + (lane & 7)]
                               [((lane >> 3) & 1) << 3]);

    uint4 ra[4], rb[4];
    // prefetch tile 0 (phase 0: Ah, Bh; kt 0)
    {
#pragma unroll
        for (int t = 0; t < 4; t++) {
            int c = t * 256 + tid;
            int row = c >> 3, kc = (c & 7) << 3;
            ra[t] = *(const uint4*)(Ah + (size_t)(mBase + row) * 256 + kc);
            rb[t] = *(const uint4*)(Bh + (size_t)(nBase + row) * 256 + kc);
        }
    }

    for (int it = 0; it < 12; it++) {
        __syncthreads();
#pragma unroll
        for (int t = 0; t < 4; t++) {
            int c = t * 256 + tid;
            int row = c >> 3, kc = (c & 7) << 3;
            *(uint4*)&As[row][kc] = ra[t];
            *(uint4*)&Bs[row][kc] = rb[t];
        }
        __syncthreads();

        if (it < 11) {
            int nx = it + 1;
            int ph = nx >> 2, kt = nx & 3;
            const __nv_bfloat16* Asrc = (ph == 1) ? Al : Ah;
            const __nv_bfloat16* Bsrc = (ph == 2) ? Bl : Bh;
#pragma unroll
            for (int t = 0; t < 4; t++) {
                int c = t * 256 + tid;
                int row = c >> 3, kc = (c & 7) << 3;
                ra[t] = *(const uint4*)(Asrc + (size_t)(mBase + row) * 256 + kt * 64 + kc);
                rb[t] = *(const uint4*)(Bsrc + (size_t)(nBase + row) * 256 + kt * 64 + kc);
            }
        }

#pragma unroll
        for (int kk = 0; kk < 4; kk++) {
            uint32_t a[2][4], b[4][4];
#pragma unroll
            for (int mi = 0; mi < 2; mi++)
                ldmatrix_x4(a[mi], a_addr[mi] + kk * 32);   // 16 bf16 = 32 bytes per k16
#pragma unroll
            for (int np = 0; np < 4; np++)
                ldmatrix_x4(b[np], b_addr[np] + kk * 32);
#pragma unroll
            for (int mi = 0; mi < 2; mi++)
#pragma unroll
                for (int ni = 0; ni < 8; ni++)
                    mma16816(acc[mi][ni], a[mi], b[ni >> 1][(ni & 1) * 2], b[ni >> 1][(ni & 1) * 2 + 1]);
        }
    }

    // ---- epilogue ----
#pragma unroll
    for (int mi = 0; mi < 2; mi++) {
#pragma unroll
        for (int half = 0; half < 2; half++) {
            int grow = mBase + warp_m * 32 + mi * 16 + (lane >> 2) + half * 8;
            int b = (grow >= NPIX) ? 1 : 0;
            int nr = grow - b * NPIX;
            if (mode == 0) {
#pragma unroll
                for (int ni = 0; ni < 8; ni++) {
                    int gc = nBase + warp_n * 64 + ni * 8 + (lane & 3) * 2;
                    float x0 = acc[mi][ni][half * 2], x1 = acc[mi][ni][half * 2 + 1];
                    int which = gc >> 8;
                    int head = (gc >> 5) & 7;
                    int d0 = gc & 31;
                    float* dst = (which == 0) ? g_q : (which == 1) ? g_k : g_v;
                    if (which < 2) {
                        int p = d0 >> 1;
                        float cv = g_cos[nr * NPAIR + p], sv = g_sin[nr * NPAIR + p];
                        float o0 = x0 * cv - x1 * sv;
                        float o1 = x1 * cv + x0 * sv;
                        x0 = o0; x1 = o1;
                    }
                    *(float2*)&dst[((size_t)(b * HEADS + head) * NPIX + nr) * HD + d0] =
                        make_float2(x0, x1);
                }
            } else {
#pragma unroll
                for (int ni = 0; ni < 8; ni++) {
                    int gc = nBase + warp_n * 64 + ni * 8 + (lane & 3) * 2;
                    float2 bv = *(const float2*)&bias[gc];
                    *(float2*)&out[(size_t)grow * 256 + gc] =
                        make_float2(acc[mi][ni][half * 2] + bv.x,
                                    acc[mi][ni][half * 2 + 1] + bv.y);
                }
            }
        }
    }
}

// ---------- neighborhood attention (lane-parallel softmax) ----------
#define AT_VS 12544
#define AT_SP 25088
#define ATTN_SMEM ((25088 + 512) * 4)

__global__ void __launch_bounds__(256) attn_kernel() {
    extern __shared__ float smf[];
    float* ks = smf;
    float* vs = smf + AT_VS;
    float* sp = smf + AT_SP;

    const int i = blockIdx.x, bh = blockIdx.y;
    const int tid = threadIdx.x, w = tid >> 5, lane = tid & 31;
    const int r0 = min(max(i - RAD, 0), HW - WIN);

    const float4* k4 = (const float4*)(g_k + ((size_t)bh * NPIX + r0 * HW) * HD);
    const float4* v4 = (const float4*)(g_v + ((size_t)bh * NPIX + r0 * HW) * HD);
    for (int idx = tid; idx < WIN * HW * HD / 4; idx += 256) {
        ((float4*)ks)[idx] = k4[idx];
        ((float4*)vs)[idx] = v4[idx];
    }
    __syncthreads();

    const float scale = 0.17677669529663688f;
    const int b = bh >> 3, h = bh & 7;

    const int kk0 = lane, kk1 = lane + 32;
    const int rr0 = kk0 / 7, cc0 = kk0 - rr0 * 7;
    const bool has1 = (kk1 < 49);
    const int rr1 = has1 ? kk1 / 7 : 0;
    const int cc1 = has1 ? (kk1 - rr1 * 7) : 0;

    for (int t = 0; t < WIN; t++) {
        const int jq = w * WIN + t;
        const float qv = g_q[((size_t)bh * NPIX + i * HW + jq) * HD + lane];
        const int c0 = min(max(jq - RAD, 0), HW - WIN);
        const int off0 = (rr0 * HW + c0 + cc0) * HD;
        const int off1 = (rr1 * HW + c0 + cc1) * HD;

        float s0 = 0.f, s1 = 0.f;
#pragma unroll
        for (int d = 0; d < 32; d++) {
            int dd = (d + lane) & 31;
            float qd = __shfl_sync(0xffffffffu, qv, d + lane);
            s0 = fmaf(qd, ks[off0 + dd], s0);
            s1 = fmaf(qd, ks[off1 + dd], s1);
        }
        s0 *= scale;
        s1 = has1 ? s1 * scale : -1e30f;

        float mx = fmaxf(s0, s1);
        mx = fmaxf(mx, __shfl_xor_sync(0xffffffffu, mx, 16));
        mx = fmaxf(mx, __shfl_xor_sync(0xffffffffu, mx, 8));
        mx = fmaxf(mx, __shfl_xor_sync(0xffffffffu, mx, 4));
        mx = fmaxf(mx, __shfl_xor_sync(0xffffffffu, mx, 2));
        mx = fmaxf(mx, __shfl_xor_sync(0xffffffffu, mx, 1));

        float p0 = __expf(s0 - mx);
        float p1 = has1 ? __expf(s1 - mx) : 0.f;
        float ls = p0 + p1;
        ls += __shfl_xor_sync(0xffffffffu, ls, 16);
        ls += __shfl_xor_sync(0xffffffffu, ls, 8);
        ls += __shfl_xor_sync(0xffffffffu, ls, 4);
        ls += __shfl_xor_sync(0xffffffffu, ls, 2);
        ls += __shfl_xor_sync(0xffffffffu, ls, 1);
        float inv = 1.0f / ls;

        sp[w * 64 + kk0] = p0 * inv;
        if (has1) sp[w * 64 + kk1] = p1 * inv;
        __syncwarp();

        float o = 0.f;
#pragma unroll
        for (int rr = 0; rr < WIN; rr++) {
            int baseo = (rr * HW + c0) * HD;
#pragma unroll
            for (int cc = 0; cc < WIN; cc++) {
                float p = sp[w * 64 + rr * WIN + cc];
                o = fmaf(p, vs[baseo + cc * HD + lane], o);
            }
        }
        size_t oi = ((size_t)b * NPIX + i * HW + jq) * CDIM + h * HD + lane;
        __nv_bfloat16 hi = __float2bfloat16(o);
        g_attnhi[oi] = hi;
        g_attnlo[oi] = __float2bfloat16(o - __bfloat162float(hi));
        __syncwarp();
    }
}

// ---------- launch ----------
extern "C" void kernel_launch(void* const* d_in, const int* in_sizes, int n_in,
                              void* d_out, int out_size) {
    const float* x     = (const float*)d_in[0];
    const float* Wqkv  = (const float*)d_in[1];
    const float* Wproj = (const float*)d_in[2];
    const float* bproj = (const float*)d_in[3];
    float* out = (float*)d_out;

    static bool attr_set = false;
    if (!attr_set) {
        cudaFuncSetAttribute(attn_kernel, cudaFuncAttributeMaxDynamicSharedMemorySize, ATTN_SMEM);
        attr_set = true;
    }

    prep_kernel<<<(SEG3 + 255) / 256, 256>>>(x, Wqkv, Wproj);
    gemm_mma<<<dim3(6, 49), 256>>>(0, bproj, out);
    attn_kernel<<<dim3(HW, BATCH * HEADS), 256, ATTN_SMEM>>>();
    gemm_mma<<<dim3(2, 49), 256>>>(1, bproj, out);
}